// round 13
// baseline (speedup 1.0000x reference)
#include <cuda_runtime.h>
#include <cstdint>

// ---------------- problem constants ----------------
#define NDST0  100000
#define NDST1  20000
#define NDST2  4096
#define NE0    1000000
#define NE1    300000
#define NE2    61440
#define D_IN   128
#define D_H    256
#define D_OUT  47

#define NB0 ((NDST0 + 255) / 256)   // 391
#define NB1 ((NDST1 + 255) / 256)   // 79
#define NB2 ((NDST2 + 255) / 256)   // 16
#define NBT (NB0 + NB1 + NB2)       // 486
#define ETOT (NE0 + NE1 + NE2)      // 1361440

// ---------------- scratch (device globals: allocation-free) ----------------
__device__ float g_h1[(size_t)NDST0 * D_H];
__device__ float g_agg1[(size_t)NDST1 * D_H];
__device__ float g_h2[(size_t)NDST1 * D_H];
__device__ float g_agg2[(size_t)NDST2 * D_H];
// per-layer CSR buffers
__device__ int g_cnt0[NDST0];
__device__ int g_cnt1[NDST1];
__device__ int g_cnt2[NDST2];
__device__ int g_rp0[NDST0 + 1];
__device__ int g_rp1[NDST1 + 1];
__device__ int g_rp2[NDST2 + 1];
__device__ int g_cur0[NDST0];
__device__ int g_cur1[NDST1];
__device__ int g_cur2[NDST2];
__device__ int g_eidx0[NE0];
__device__ int g_eidx1[NE1];
__device__ int g_eidx2[NE2];
__device__ int g_bsum0[NB0];
__device__ int g_bsum1[NB1];
__device__ int g_bsum2[NB2];
// transposed/concat weights: Bt[n][k2] = (k2<K ? Ws[k2][n] : Wn[k2-K][n])
__device__ float g_Bt0[(size_t)256 * 256];
__device__ float g_Bt1[(size_t)256 * 512];
__device__ float g_Bt2[(size_t)64 * 512];

// ---------------- helpers ----------------
__device__ __forceinline__ uint32_t smem_u32(const void* p) {
    uint32_t a;
    asm("{ .reg .u64 t; cvta.to.shared.u64 t, %1; cvt.u32.u64 %0, t; }"
        : "=r"(a) : "l"(p));
    return a;
}

__device__ __forceinline__ void cp16(uint32_t dst, const float* src, int sz) {
    asm volatile("cp.async.cg.shared.global [%0], [%1], 16, %2;"
                 :: "r"(dst), "l"(src), "r"(sz));
}

__device__ __forceinline__ uint32_t f2tf32(float f) {
    uint32_t r;
    asm("cvt.rna.tf32.f32 %0, %1;" : "=r"(r) : "f"(f));
    return r;
}

__device__ __forceinline__ void mma_tf32(float* c, const uint32_t* a, const uint32_t* b) {
    asm volatile(
        "mma.sync.aligned.m16n8k8.row.col.f32.tf32.tf32.f32 "
        "{%0,%1,%2,%3}, {%4,%5,%6,%7}, {%8,%9}, {%0,%1,%2,%3};"
        : "+f"(c[0]), "+f"(c[1]), "+f"(c[2]), "+f"(c[3])
        : "r"(a[0]), "r"(a[1]), "r"(a[2]), "r"(a[3]), "r"(b[0]), "r"(b[1]));
}

// ---------------- batched CSR build ----------------
__global__ void zero_all_kernel() {
    int i = blockIdx.x * blockDim.x + threadIdx.x;
    if (i < NDST0) g_cnt0[i] = 0;
    else if (i < NDST0 + NDST1) g_cnt1[i - NDST0] = 0;
    else if (i < NDST0 + NDST1 + NDST2) g_cnt2[i - NDST0 - NDST1] = 0;
}

__global__ void hist_all_kernel(const int* __restrict__ d0, const int* __restrict__ d1,
                                const int* __restrict__ d2) {
    int i = blockIdx.x * blockDim.x + threadIdx.x;
    if (i < NE0) atomicAdd(&g_cnt0[d0[i]], 1);
    else if (i < NE0 + NE1) atomicAdd(&g_cnt1[d1[i - NE0]], 1);
    else if (i < ETOT) atomicAdd(&g_cnt2[d2[i - NE0 - NE1]], 1);
}

// per-256-block sums, 486 blocks across the 3 layers
__global__ void scan1_all_kernel() {
    const int* cnt; int* bsum; int n; int lb;
    int b = blockIdx.x;
    if (b < NB0)            { cnt = g_cnt0; bsum = g_bsum0; n = NDST0; lb = b; }
    else if (b < NB0 + NB1) { cnt = g_cnt1; bsum = g_bsum1; n = NDST1; lb = b - NB0; }
    else                    { cnt = g_cnt2; bsum = g_bsum2; n = NDST2; lb = b - NB0 - NB1; }
    __shared__ int s[8];
    int i = lb * 256 + threadIdx.x;
    int v = (i < n) ? cnt[i] : 0;
    #pragma unroll
    for (int o = 16; o; o >>= 1) v += __shfl_down_sync(~0u, v, o);
    if ((threadIdx.x & 31) == 0) s[threadIdx.x >> 5] = v;
    __syncthreads();
    if (threadIdx.x < 8) {
        int x = s[threadIdx.x];
        #pragma unroll
        for (int o = 4; o; o >>= 1) x += __shfl_down_sync(0xff, x, o);
        if (threadIdx.x == 0) bsum[lb] = x;
    }
}

// merged scan2+scan3: each block computes its bsum prefix (coalesced warp sum),
// then does its local exclusive scan. 486 blocks.
__global__ void scan23_all_kernel() {
    const int* cnt; const int* bsum; int* rowptr; int* cur; int n; int E; int lb;
    int b = blockIdx.x;
    if (b < NB0)            { cnt = g_cnt0; bsum = g_bsum0; rowptr = g_rp0; cur = g_cur0;
                              n = NDST0; E = NE0; lb = b; }
    else if (b < NB0 + NB1) { cnt = g_cnt1; bsum = g_bsum1; rowptr = g_rp1; cur = g_cur1;
                              n = NDST1; E = NE1; lb = b - NB0; }
    else                    { cnt = g_cnt2; bsum = g_bsum2; rowptr = g_rp2; cur = g_cur2;
                              n = NDST2; E = NE2; lb = b - NB0 - NB1; }
    __shared__ int s[256];
    __shared__ int off;
    int t = threadIdx.x;
    int i = lb * 256 + t;
    int v = (i < n) ? cnt[i] : 0;
    s[t] = v;
    // warp 0: exclusive prefix of block sums over [0, lb)
    if (t < 32) {
        int sum = 0;
        for (int k = t; k < lb; k += 32) sum += bsum[k];
        #pragma unroll
        for (int o = 16; o; o >>= 1) sum += __shfl_down_sync(~0u, sum, o);
        if (t == 0) off = sum;
    }
    __syncthreads();
    for (int o = 1; o < 256; o <<= 1) {
        int u = (t >= o) ? s[t - o] : 0;
        __syncthreads();
        s[t] += u;
        __syncthreads();
    }
    int ex = s[t] - v + off;
    if (i < n) { rowptr[i] = ex; cur[i] = ex; }
    if (i == 0) rowptr[n] = E;
}

__global__ void fillidx_all_kernel(const int* __restrict__ s0, const int* __restrict__ d0,
                                   const int* __restrict__ s1, const int* __restrict__ d1,
                                   const int* __restrict__ s2, const int* __restrict__ d2) {
    int i = blockIdx.x * blockDim.x + threadIdx.x;
    if (i < NE0) {
        int p = atomicAdd(&g_cur0[d0[i]], 1);
        g_eidx0[p] = s0[i];
    } else if (i < NE0 + NE1) {
        int j = i - NE0;
        int p = atomicAdd(&g_cur1[d1[j]], 1);
        g_eidx1[p] = s1[j];
    } else if (i < ETOT) {
        int j = i - NE0 - NE1;
        int p = atomicAdd(&g_cur2[d2[j]], 1);
        g_eidx2[p] = s2[j];
    }
}

// ---------------- gather aggregation: one warp per dst row (unroll-2, proven) ----------------
template<int V>
__global__ __launch_bounds__(256) void gather_agg_kernel(
    const float4* __restrict__ feat, const int* __restrict__ rowptr,
    const int* __restrict__ eidx, float4* __restrict__ agg, int n_dst)
{
    int w = (blockIdx.x * blockDim.x + threadIdx.x) >> 5;
    if (w >= n_dst) return;
    int lane = threadIdx.x & 31;
    int beg = rowptr[w], end = rowptr[w + 1];

    float4 acc[V];
    #pragma unroll
    for (int v = 0; v < V; v++) acc[v] = make_float4(0.f, 0.f, 0.f, 0.f);

    int j = beg;
    for (; j + 1 < end; j += 2) {
        int s0 = eidx[j], s1 = eidx[j + 1];
        #pragma unroll
        for (int v = 0; v < V; v++) {
            float4 f0 = feat[(size_t)s0 * (32 * V) + v * 32 + lane];
            float4 f1 = feat[(size_t)s1 * (32 * V) + v * 32 + lane];
            acc[v].x += f0.x + f1.x;
            acc[v].y += f0.y + f1.y;
            acc[v].z += f0.z + f1.z;
            acc[v].w += f0.w + f1.w;
        }
    }
    if (j < end) {
        int s0 = eidx[j];
        #pragma unroll
        for (int v = 0; v < V; v++) {
            float4 f0 = feat[(size_t)s0 * (32 * V) + v * 32 + lane];
            acc[v].x += f0.x; acc[v].y += f0.y; acc[v].z += f0.z; acc[v].w += f0.w;
        }
    }

    float inv = 1.0f / (float)max(end - beg, 1);
    #pragma unroll
    for (int v = 0; v < V; v++) {
        float4 o;
        o.x = acc[v].x * inv; o.y = acc[v].y * inv;
        o.z = acc[v].z * inv; o.w = acc[v].w * inv;
        agg[(size_t)w * (32 * V) + v * 32 + lane] = o;
    }
}

// ---------------- batched Bt build (one launch) ----------------
__global__ void build_bt_all_kernel(const float* __restrict__ Ws0, const float* __restrict__ Wn0,
                                    const float* __restrict__ Ws1, const float* __restrict__ Wn1,
                                    const float* __restrict__ Ws2, const float* __restrict__ Wn2) {
    long long i = (long long)blockIdx.x * blockDim.x + threadIdx.x;
    const float *Ws, *Wn; float* Bt; int K, N_out; long long j;
    if (i < 65536)                 { Ws = Ws0; Wn = Wn0; Bt = g_Bt0; K = 128; N_out = 256; j = i; }
    else if (i < 65536 + 131072)   { Ws = Ws1; Wn = Wn1; Bt = g_Bt1; K = 256; N_out = 256; j = i - 65536; }
    else if (i < 65536 + 131072 + 32768)
                                   { Ws = Ws2; Wn = Wn2; Bt = g_Bt2; K = 256; N_out = 47;  j = i - 65536 - 131072; }
    else return;
    int K2 = 2 * K;
    int n = (int)(j / K2);
    int k2 = (int)(j % K2);
    float v = 0.f;
    if (n < N_out)
        v = (k2 < K) ? Ws[(size_t)k2 * N_out + n] : Wn[(size_t)(k2 - K) * N_out + n];
    Bt[j] = v;
}

#define LDS_P 36

// ---------------- FUSED layer-0 gather + GEMM ----------------
// Phase 1: each CTA gathers neighbor means for its 128 rows into smem agg
// buffer laid out exactly like the As chunks ([chunk][row][LDS_P]).
// Phase 2: standard mainloop; chunks 0-3 (dst half) cp.async from x,
// chunks 4-7 (neighbor half) read A fragments straight from the agg buffer.
// K=128, NPAD=256 hardcoded.
#define F_AGG_F   (4 * 128 * LDS_P)                  // 18432 floats
#define F_AS_F    (2 * 128 * LDS_P)                  // 9216
#define F_BS_F    (2 * 256 * LDS_P)                  // 18432
#define SMEM_FUSED ((F_AGG_F + F_AS_F + F_BS_F) * 4) // 184320 bytes

__global__ __launch_bounds__(256, 1) void sage_gemm_fused0(
    const float* __restrict__ x, const int* __restrict__ rowptr,
    const int* __restrict__ eidx, const float* __restrict__ Bt,
    const float* __restrict__ bias, float* __restrict__ out, int M)
{
    constexpr int NT = 8;            // 256/32
    constexpr int K = 128, K2 = 256, nc = 8;
    extern __shared__ float smem[];
    float* aggBase = smem;                   // [4][128][LDS_P]
    float* AsBase  = smem + F_AGG_F;         // [2][128][LDS_P]
    float* BsBase  = smem + F_AGG_F + F_AS_F;// [2][256][LDS_P]

    const uint32_t sb_a = smem_u32(AsBase);
    const uint32_t sb_b = smem_u32(BsBase);
    const int tid = threadIdx.x;
    const int wid = tid >> 5, lane = tid & 31;
    const int g = lane >> 2, tg = lane & 3;
    const int wm = wid & 1, wn = wid >> 1;
    const int m0 = blockIdx.x * 128;

    auto issue = [&](int ic) {
        const int buf = ic & 1;
        const int kb_b = ic * 32;
        if (ic < 4) {   // dst half: A from x
            #pragma unroll
            for (int t = 0; t < 4; t++) {
                int idx = tid + t * 256;
                int r = idx >> 3, q = idx & 7;
                int gr = m0 + r;
                int grc = gr < M ? gr : (M - 1);
                const float* src = x + (size_t)grc * K + kb_b + q * 4;
                uint32_t dst = sb_a + (uint32_t)((buf * 128 + r) * LDS_P + q * 4) * 4u;
                cp16(dst, src, gr < M ? 16 : 0);
            }
        }
        #pragma unroll
        for (int t = 0; t < 8; t++) {
            int idx = tid + t * 256;
            int n = idx >> 3, q = idx & 7;
            const float* src = Bt + (size_t)n * K2 + kb_b + q * 4;
            uint32_t dst = sb_b + (uint32_t)((buf * 256 + n) * LDS_P + q * 4) * 4u;
            cp16(dst, src, 16);
        }
        asm volatile("cp.async.commit_group;" ::: "memory");
    };

    // prefetch chunk 0 while gathering
    issue(0);

    // ---- phase 1: gather neighbor means into aggBase ----
    {
        const float4* feat = (const float4*)x;
        #pragma unroll 1
        for (int r16 = 0; r16 < 16; r16++) {
            int r = wid * 16 + r16;
            int gr = m0 + r;
            float4 acc = make_float4(0.f, 0.f, 0.f, 0.f);
            if (gr < M) {
                int beg = rowptr[gr], end = rowptr[gr + 1];
                int j = beg;
                for (; j + 1 < end; j += 2) {
                    int s0 = eidx[j], s1 = eidx[j + 1];
                    float4 f0 = feat[(size_t)s0 * 32 + lane];
                    float4 f1 = feat[(size_t)s1 * 32 + lane];
                    acc.x += f0.x + f1.x;
                    acc.y += f0.y + f1.y;
                    acc.z += f0.z + f1.z;
                    acc.w += f0.w + f1.w;
                }
                if (j < end) {
                    int s0 = eidx[j];
                    float4 f0 = feat[(size_t)s0 * 32 + lane];
                    acc.x += f0.x; acc.y += f0.y; acc.z += f0.z; acc.w += f0.w;
                }
                float inv = 1.0f / (float)max(end - beg, 1);
                acc.x *= inv; acc.y *= inv; acc.z *= inv; acc.w *= inv;
            }
            // lane covers k = 4*lane..4*lane+3 -> chunk = lane/8, koff = 4*(lane%8)
            int chunk = lane >> 3;
            int koff = (lane & 7) * 4;
            *(float4*)(aggBase + chunk * 128 * LDS_P + r * LDS_P + koff) = acc;
        }
    }
    __syncthreads();

    float acc[4][NT][4];
    #pragma unroll
    for (int m = 0; m < 4; m++)
        #pragma unroll
        for (int n = 0; n < NT; n++)
            #pragma unroll
            for (int j = 0; j < 4; j++) acc[m][n][j] = 0.f;

    for (int ic = 0; ic < nc; ic++) {
        if (ic + 1 < nc) {
            issue(ic + 1);
            asm volatile("cp.async.wait_group 1;" ::: "memory");
        } else {
            asm volatile("cp.async.wait_group 0;" ::: "memory");
        }
        __syncthreads();

        const float* a_ = (ic < 4) ? (AsBase + (ic & 1) * 128 * LDS_P)
                                   : (aggBase + (ic - 4) * 128 * LDS_P);
        const float* b_ = BsBase + (ic & 1) * 256 * LDS_P;

        #pragma unroll
        for (int s = 0; s < 4; s++) {
            const int c = s * 8 + tg;
            uint32_t af[4][4];
            #pragma unroll
            for (int m = 0; m < 4; m++) {
                int r = wm * 64 + m * 16 + g;
                af[m][0] = f2tf32(a_[r * LDS_P + c]);
                af[m][1] = f2tf32(a_[(r + 8) * LDS_P + c]);
                af[m][2] = f2tf32(a_[r * LDS_P + c + 4]);
                af[m][3] = f2tf32(a_[(r + 8) * LDS_P + c + 4]);
            }
            uint32_t bf[NT][2];
            #pragma unroll
            for (int n = 0; n < NT; n++) {
                int nn = wn * 64 + n * 8 + g;
                bf[n][0] = f2tf32(b_[nn * LDS_P + c]);
                bf[n][1] = f2tf32(b_[nn * LDS_P + c + 4]);
            }
            #pragma unroll
            for (int m = 0; m < 4; m++)
                #pragma unroll
                for (int n = 0; n < NT; n++)
                    mma_tf32(acc[m][n], af[m], bf[n]);
        }
        __syncthreads();
    }

    #pragma unroll
    for (int m = 0; m < 4; m++) {
        const int r0 = m0 + wm * 64 + m * 16 + g;
        #pragma unroll
        for (int n = 0; n < NT; n++) {
            const int c0 = wn * 64 + n * 8 + tg * 2;
            #pragma unroll
            for (int i = 0; i < 2; i++) {
                const int r = r0 + i * 8;
                if (r >= M) continue;
                #pragma unroll
                for (int j = 0; j < 2; j++) {
                    const int cc = c0 + j;
                    float v = acc[m][n][i * 2 + j] + bias[cc];
                    v = fmaxf(v, 0.f);
                    out[(size_t)r * 256 + cc] = v;
                }
            }
        }
    }
}

// ---------------- mma.sync tf32 fused SAGE GEMM (R6-exact, layers 1/2) ----------------
template<int NPAD>
__global__ __launch_bounds__(256, 1) void sage_gemm_mma(
    const float* __restrict__ Adst, const float* __restrict__ Agg,
    const float* __restrict__ Bt, const float* __restrict__ bias,
    float* __restrict__ out, int M, int K, int N_out, int relu)
{
    constexpr int NT = NPAD / 32;
    extern __shared__ float smem[];
    float* AsBase = smem;
    float* BsBase = smem + 2 * 128 * LDS_P;

    const uint32_t sb = smem_u32(smem);
    const uint32_t sb_b = sb + 2u * 128u * LDS_P * 4u;
    const int tid = threadIdx.x;
    const int wid = tid >> 5, lane = tid & 31;
    const int g = lane >> 2, tg = lane & 3;
    const int wm = wid & 1, wn = wid >> 1;
    const int m0 = blockIdx.x * 128;
    const int K2 = 2 * K;
    const int nc = K2 / 32;

    float acc[4][NT][4];
    #pragma unroll
    for (int m = 0; m < 4; m++)
        #pragma unroll
        for (int n = 0; n < NT; n++)
            #pragma unroll
            for (int j = 0; j < 4; j++) acc[m][n][j] = 0.f;

    auto issue = [&](int ic) {
        const int buf = ic & 1;
        const int kb_b = ic * 32;
        int kb = kb_b;
        const float* __restrict__ Ap = Adst;
        if (kb >= K) { Ap = Agg; kb -= K; }
        #pragma unroll
        for (int t = 0; t < 4; t++) {
            int idx = tid + t * 256;
            int r = idx >> 3, q = idx & 7;
            int gr = m0 + r;
            int grc = gr < M ? gr : (M - 1);
            const float* src = Ap + (size_t)grc * K + kb + q * 4;
            uint32_t dst = sb + (uint32_t)((buf * 128 + r) * LDS_P + q * 4) * 4u;
            cp16(dst, src, gr < M ? 16 : 0);
        }
        #pragma unroll
        for (int t = 0; t < NPAD / 32; t++) {
            int idx = tid + t * 256;
            int n = idx >> 3, q = idx & 7;
            const float* src = Bt + (size_t)n * K2 + kb_b + q * 4;
            uint32_t dst = sb_b + (uint32_t)((buf * NPAD + n) * LDS_P + q * 4) * 4u;
            cp16(dst, src, 16);
        }
        asm volatile("cp.async.commit_group;" ::: "memory");
    };

    issue(0);
    for (int ic = 0; ic < nc; ic++) {
        if (ic + 1 < nc) {
            issue(ic + 1);
            asm volatile("cp.async.wait_group 1;" ::: "memory");
        } else {
            asm volatile("cp.async.wait_group 0;" ::: "memory");
        }
        __syncthreads();

        const float* a_ = AsBase + (ic & 1) * 128 * LDS_P;
        const float* b_ = BsBase + (ic & 1) * NPAD * LDS_P;

        #pragma unroll
        for (int s = 0; s < 4; s++) {
            const int c = s * 8 + tg;
            uint32_t af[4][4];
            #pragma unroll
            for (int m = 0; m < 4; m++) {
                int r = wm * 64 + m * 16 + g;
                af[m][0] = f2tf32(a_[r * LDS_P + c]);
                af[m][1] = f2tf32(a_[(r + 8) * LDS_P + c]);
                af[m][2] = f2tf32(a_[r * LDS_P + c + 4]);
                af[m][3] = f2tf32(a_[(r + 8) * LDS_P + c + 4]);
            }
            uint32_t bf[NT][2];
            #pragma unroll
            for (int n = 0; n < NT; n++) {
                int nn = wn * (NPAD / 4) + n * 8 + g;
                bf[n][0] = f2tf32(b_[nn * LDS_P + c]);
                bf[n][1] = f2tf32(b_[nn * LDS_P + c + 4]);
            }
            #pragma unroll
            for (int m = 0; m < 4; m++)
                #pragma unroll
                for (int n = 0; n < NT; n++)
                    mma_tf32(acc[m][n], af[m], bf[n]);
        }
        __syncthreads();
    }

    #pragma unroll
    for (int m = 0; m < 4; m++) {
        const int r0 = m0 + wm * 64 + m * 16 + g;
        #pragma unroll
        for (int n = 0; n < NT; n++) {
            const int c0 = wn * (NPAD / 4) + n * 8 + tg * 2;
            #pragma unroll
            for (int i = 0; i < 2; i++) {
                const int r = r0 + i * 8;
                if (r >= M) continue;
                #pragma unroll
                for (int j = 0; j < 2; j++) {
                    const int cc = c0 + j;
                    if (cc >= N_out) continue;
                    float v = acc[m][n][i * 2 + j] + bias[cc];
                    if (relu) v = fmaxf(v, 0.f);
                    out[(size_t)r * N_out + cc] = v;
                }
            }
        }
    }
}

#define SMEM256 ((2 * 128 * LDS_P + 2 * 256 * LDS_P) * 4)
#define SMEM64  ((2 * 128 * LDS_P + 2 * 64 * LDS_P) * 4)

// ---------------- host orchestration ----------------
extern "C" void kernel_launch(void* const* d_in, const int* in_sizes, int n_in,
                              void* d_out, int out_size) {
    const float* x    = (const float*)d_in[0];
    const int*   src0 = (const int*)  d_in[1];
    const int*   dst0 = (const int*)  d_in[2];
    const int*   src1 = (const int*)  d_in[3];
    const int*   dst1 = (const int*)  d_in[4];
    const int*   src2 = (const int*)  d_in[5];
    const int*   dst2 = (const int*)  d_in[6];
    const float* Ws0  = (const float*)d_in[7];
    const float* Wn0  = (const float*)d_in[8];
    const float* b0   = (const float*)d_in[9];
    const float* Ws1  = (const float*)d_in[10];
    const float* Wn1  = (const float*)d_in[11];
    const float* b1   = (const float*)d_in[12];
    const float* Ws2  = (const float*)d_in[13];
    const float* Wn2  = (const float*)d_in[14];
    const float* b2   = (const float*)d_in[15];
    float* out = (float*)d_out;

    float *h1, *agg1, *h2, *agg2, *bt0, *bt1, *bt2;
    int *rp0, *rp1, *rp2, *ei0, *ei1, *ei2;
    cudaGetSymbolAddress((void**)&h1,   g_h1);
    cudaGetSymbolAddress((void**)&agg1, g_agg1);
    cudaGetSymbolAddress((void**)&h2,   g_h2);
    cudaGetSymbolAddress((void**)&agg2, g_agg2);
    cudaGetSymbolAddress((void**)&rp0, g_rp0);
    cudaGetSymbolAddress((void**)&rp1, g_rp1);
    cudaGetSymbolAddress((void**)&rp2, g_rp2);
    cudaGetSymbolAddress((void**)&ei0, g_eidx0);
    cudaGetSymbolAddress((void**)&ei1, g_eidx1);
    cudaGetSymbolAddress((void**)&ei2, g_eidx2);
    cudaGetSymbolAddress((void**)&bt0, g_Bt0);
    cudaGetSymbolAddress((void**)&bt1, g_Bt1);
    cudaGetSymbolAddress((void**)&bt2, g_Bt2);

    cudaFuncSetAttribute(sage_gemm_fused0,
                         cudaFuncAttributeMaxDynamicSharedMemorySize, SMEM_FUSED);
    cudaFuncSetAttribute(sage_gemm_mma<256>,
                         cudaFuncAttributeMaxDynamicSharedMemorySize, SMEM256);
    cudaFuncSetAttribute(sage_gemm_mma<64>,
                         cudaFuncAttributeMaxDynamicSharedMemorySize, SMEM64);

    const int TB = 256;
    const int NTOT = NDST0 + NDST1 + NDST2;
    const int BT_TOT = 65536 + 131072 + 32768;

    // ---- batched CSR build for ALL layers ----
    zero_all_kernel<<<(NTOT + TB - 1) / TB, TB>>>();
    hist_all_kernel<<<(ETOT + TB - 1) / TB, TB>>>(dst0, dst1, dst2);
    scan1_all_kernel<<<NBT, TB>>>();
    scan23_all_kernel<<<NBT, TB>>>();
    fillidx_all_kernel<<<(ETOT + TB - 1) / TB, TB>>>(src0, dst0, src1, dst1, src2, dst2);

    // ---- batched weight transpose ----
    build_bt_all_kernel<<<(BT_TOT + TB - 1) / TB, TB>>>(Ws0, Wn0, Ws1, Wn1, Ws2, Wn2);

    // ---- layer 0 (FUSED gather+GEMM): x -> h1, relu ----
    sage_gemm_fused0<<<(NDST0 + 127) / 128, 256, SMEM_FUSED>>>(
        x, rp0, ei0, bt0, b0, h1, NDST0);

    // ---- layer 1: h1[100000,256] -> h2[20000,256], relu ----
    gather_agg_kernel<2><<<(NDST1 * 32 + TB - 1) / TB, TB>>>(
        (const float4*)h1, rp1, ei1, (float4*)agg1, NDST1);
    sage_gemm_mma<256><<<(NDST1 + 127) / 128, 256, SMEM256>>>(
        h1, agg1, bt1, b1, h2, NDST1, D_H, 256, 1);

    // ---- layer 2: h2[20000,256] -> out[4096,47], no relu ----
    gather_agg_kernel<2><<<(NDST2 * 32 + TB - 1) / TB, TB>>>(
        (const float4*)h2, rp2, ei2, (float4*)agg2, NDST2);
    sage_gemm_mma<64><<<(NDST2 + 127) / 128, 256, SMEM64>>>(
        h2, agg2, bt2, b2, out, NDST2, D_H, 47, 0);
}

// round 14
// speedup vs baseline: 1.3354x; 1.3354x over previous
#include <cuda_runtime.h>
#include <cstdint>

// ---------------- problem constants ----------------
#define NDST0  100000
#define NDST1  20000
#define NDST2  4096
#define NE0    1000000
#define NE1    300000
#define NE2    61440
#define D_IN   128
#define D_H    256
#define D_OUT  47

#define NB0 ((NDST0 + 255) / 256)   // 391
#define NB1 ((NDST1 + 255) / 256)   // 79
#define NB2 ((NDST2 + 255) / 256)   // 16
#define NBT (NB0 + NB1 + NB2)       // 486
#define ETOT (NE0 + NE1 + NE2)      // 1361440
#define NTOT (NDST0 + NDST1 + NDST2)

// ---------------- scratch (device globals: allocation-free) ----------------
__device__ float g_agg0[(size_t)NDST0 * D_IN];
__device__ float g_h1[(size_t)NDST0 * D_H];
__device__ float g_agg1[(size_t)NDST1 * D_H];
__device__ float g_h2[(size_t)NDST1 * D_H];
__device__ float g_agg2[(size_t)NDST2 * D_H];
// per-layer CSR buffers
__device__ int g_cnt0[NDST0];
__device__ int g_cnt1[NDST1];
__device__ int g_cnt2[NDST2];
__device__ int g_rp0[NDST0 + 1];
__device__ int g_rp1[NDST1 + 1];
__device__ int g_rp2[NDST2 + 1];
__device__ int g_cur0[NDST0];
__device__ int g_cur1[NDST1];
__device__ int g_cur2[NDST2];
__device__ int g_eidx0[NE0];
__device__ int g_eidx1[NE1];
__device__ int g_eidx2[NE2];
__device__ int g_bsum0[NB0];
__device__ int g_bsum1[NB1];
__device__ int g_bsum2[NB2];
// transposed/concat weights: Bt[n][k2] = (k2<K ? Ws[k2][n] : Wn[k2-K][n])
__device__ float g_Bt0[(size_t)256 * 256];
__device__ float g_Bt1[(size_t)256 * 512];
__device__ float g_Bt2[(size_t)64 * 512];

// ---------------- helpers ----------------
__device__ __forceinline__ uint32_t smem_u32(const void* p) {
    uint32_t a;
    asm("{ .reg .u64 t; cvta.to.shared.u64 t, %1; cvt.u32.u64 %0, t; }"
        : "=r"(a) : "l"(p));
    return a;
}

__device__ __forceinline__ void cp16(uint32_t dst, const float* src, int sz) {
    asm volatile("cp.async.cg.shared.global [%0], [%1], 16, %2;"
                 :: "r"(dst), "l"(src), "r"(sz));
}

__device__ __forceinline__ uint32_t f2tf32(float f) {
    uint32_t r;
    asm("cvt.rna.tf32.f32 %0, %1;" : "=r"(r) : "f"(f));
    return r;
}

__device__ __forceinline__ void mma_tf32(float* c, const uint32_t* a, const uint32_t* b) {
    asm volatile(
        "mma.sync.aligned.m16n8k8.row.col.f32.tf32.tf32.f32 "
        "{%0,%1,%2,%3}, {%4,%5,%6,%7}, {%8,%9}, {%0,%1,%2,%3};"
        : "+f"(c[0]), "+f"(c[1]), "+f"(c[2]), "+f"(c[3])
        : "r"(a[0]), "r"(a[1]), "r"(a[2]), "r"(a[3]), "r"(b[0]), "r"(b[1]));
}

// ---------------- batched Bt build + cnt zero (one launch, runs before hist) ----------------
// bt seg sizes: L0 256*256=65536, L1 256*512=131072, L2 64*512=32768 -> 229376
__global__ void build_bt_zero_kernel(const float* __restrict__ Ws0, const float* __restrict__ Wn0,
                                     const float* __restrict__ Ws1, const float* __restrict__ Wn1,
                                     const float* __restrict__ Ws2, const float* __restrict__ Wn2) {
    long long i = (long long)blockIdx.x * blockDim.x + threadIdx.x;
    // zero cnt arrays (NTOT = 124096 <= grid coverage)
    if (i < NDST0) g_cnt0[i] = 0;
    else if (i < NDST0 + NDST1) g_cnt1[i - NDST0] = 0;
    else if (i < NTOT) g_cnt2[i - NDST0 - NDST1] = 0;

    if (i >= 65536 + 131072 + 32768) return;
    const float *Ws, *Wn; float* Bt; int K, N_out; long long j;
    if (i < 65536)               { Ws = Ws0; Wn = Wn0; Bt = g_Bt0; K = 128; N_out = 256; j = i; }
    else if (i < 65536 + 131072) { Ws = Ws1; Wn = Wn1; Bt = g_Bt1; K = 256; N_out = 256; j = i - 65536; }
    else                         { Ws = Ws2; Wn = Wn2; Bt = g_Bt2; K = 256; N_out = 47;  j = i - 65536 - 131072; }
    int K2 = 2 * K;
    int n = (int)(j / K2);
    int k2 = (int)(j % K2);
    float v = 0.f;
    if (n < N_out)
        v = (k2 < K) ? Ws[(size_t)k2 * N_out + n] : Wn[(size_t)(k2 - K) * N_out + n];
    Bt[j] = v;
}

// ---------------- batched CSR build ----------------
__global__ void hist_all_kernel(const int* __restrict__ d0, const int* __restrict__ d1,
                                const int* __restrict__ d2) {
    int i = blockIdx.x * blockDim.x + threadIdx.x;
    if (i < NE0) atomicAdd(&g_cnt0[d0[i]], 1);
    else if (i < NE0 + NE1) atomicAdd(&g_cnt1[d1[i - NE0]], 1);
    else if (i < ETOT) atomicAdd(&g_cnt2[d2[i - NE0 - NE1]], 1);
}

// per-256-block sums, 486 blocks across the 3 layers
__global__ void scan1_all_kernel() {
    const int* cnt; int* bsum; int n; int lb;
    int b = blockIdx.x;
    if (b < NB0)            { cnt = g_cnt0; bsum = g_bsum0; n = NDST0; lb = b; }
    else if (b < NB0 + NB1) { cnt = g_cnt1; bsum = g_bsum1; n = NDST1; lb = b - NB0; }
    else                    { cnt = g_cnt2; bsum = g_bsum2; n = NDST2; lb = b - NB0 - NB1; }
    __shared__ int s[8];
    int i = lb * 256 + threadIdx.x;
    int v = (i < n) ? cnt[i] : 0;
    #pragma unroll
    for (int o = 16; o; o >>= 1) v += __shfl_down_sync(~0u, v, o);
    if ((threadIdx.x & 31) == 0) s[threadIdx.x >> 5] = v;
    __syncthreads();
    if (threadIdx.x < 8) {
        int x = s[threadIdx.x];
        #pragma unroll
        for (int o = 4; o; o >>= 1) x += __shfl_down_sync(0xff, x, o);
        if (threadIdx.x == 0) bsum[lb] = x;
    }
}

// merged scan2+scan3 (R13-measured fine): each block computes its bsum prefix
// with a coalesced warp-strided sum, then its local exclusive scan. 486 blocks.
__global__ void scan23_all_kernel() {
    const int* cnt; const int* bsum; int* rowptr; int* cur; int n; int E; int lb;
    int b = blockIdx.x;
    if (b < NB0)            { cnt = g_cnt0; bsum = g_bsum0; rowptr = g_rp0; cur = g_cur0;
                              n = NDST0; E = NE0; lb = b; }
    else if (b < NB0 + NB1) { cnt = g_cnt1; bsum = g_bsum1; rowptr = g_rp1; cur = g_cur1;
                              n = NDST1; E = NE1; lb = b - NB0; }
    else                    { cnt = g_cnt2; bsum = g_bsum2; rowptr = g_rp2; cur = g_cur2;
                              n = NDST2; E = NE2; lb = b - NB0 - NB1; }
    __shared__ int s[256];
    __shared__ int off;
    int t = threadIdx.x;
    int i = lb * 256 + t;
    int v = (i < n) ? cnt[i] : 0;
    s[t] = v;
    if (t < 32) {
        int sum = 0;
        for (int k = t; k < lb; k += 32) sum += bsum[k];
        #pragma unroll
        for (int o = 16; o; o >>= 1) sum += __shfl_down_sync(~0u, sum, o);
        if (t == 0) off = sum;
    }
    __syncthreads();
    for (int o = 1; o < 256; o <<= 1) {
        int u = (t >= o) ? s[t - o] : 0;
        __syncthreads();
        s[t] += u;
        __syncthreads();
    }
    int ex = s[t] - v + off;
    if (i < n) { rowptr[i] = ex; cur[i] = ex; }
    if (i == 0) rowptr[n] = E;
}

__global__ void fillidx_all_kernel(const int* __restrict__ s0, const int* __restrict__ d0,
                                   const int* __restrict__ s1, const int* __restrict__ d1,
                                   const int* __restrict__ s2, const int* __restrict__ d2) {
    int i = blockIdx.x * blockDim.x + threadIdx.x;
    if (i < NE0) {
        int p = atomicAdd(&g_cur0[d0[i]], 1);
        g_eidx0[p] = s0[i];
    } else if (i < NE0 + NE1) {
        int j = i - NE0;
        int p = atomicAdd(&g_cur1[d1[j]], 1);
        g_eidx1[p] = s1[j];
    } else if (i < ETOT) {
        int j = i - NE0 - NE1;
        int p = atomicAdd(&g_cur2[d2[j]], 1);
        g_eidx2[p] = s2[j];
    }
}

// ---------------- gather aggregation: one warp per dst row (unroll-2, R12-proven) ----------------
template<int V>
__global__ __launch_bounds__(256) void gather_agg_kernel(
    const float4* __restrict__ feat, const int* __restrict__ rowptr,
    const int* __restrict__ eidx, float4* __restrict__ agg, int n_dst)
{
    int w = (blockIdx.x * blockDim.x + threadIdx.x) >> 5;
    if (w >= n_dst) return;
    int lane = threadIdx.x & 31;
    int beg = rowptr[w], end = rowptr[w + 1];

    float4 acc[V];
    #pragma unroll
    for (int v = 0; v < V; v++) acc[v] = make_float4(0.f, 0.f, 0.f, 0.f);

    int j = beg;
    for (; j + 1 < end; j += 2) {
        int s0 = eidx[j], s1 = eidx[j + 1];
        #pragma unroll
        for (int v = 0; v < V; v++) {
            float4 f0 = feat[(size_t)s0 * (32 * V) + v * 32 + lane];
            float4 f1 = feat[(size_t)s1 * (32 * V) + v * 32 + lane];
            acc[v].x += f0.x + f1.x;
            acc[v].y += f0.y + f1.y;
            acc[v].z += f0.z + f1.z;
            acc[v].w += f0.w + f1.w;
        }
    }
    if (j < end) {
        int s0 = eidx[j];
        #pragma unroll
        for (int v = 0; v < V; v++) {
            float4 f0 = feat[(size_t)s0 * (32 * V) + v * 32 + lane];
            acc[v].x += f0.x; acc[v].y += f0.y; acc[v].z += f0.z; acc[v].w += f0.w;
        }
    }

    float inv = 1.0f / (float)max(end - beg, 1);
    #pragma unroll
    for (int v = 0; v < V; v++) {
        float4 o;
        o.x = acc[v].x * inv; o.y = acc[v].y * inv;
        o.z = acc[v].z * inv; o.w = acc[v].w * inv;
        agg[(size_t)w * (32 * V) + v * 32 + lane] = o;
    }
}

// ---------------- mma.sync tf32 fused SAGE GEMM (R6-exact) ----------------
#define LDS_P 36

template<int NPAD>
__global__ __launch_bounds__(256, 1) void sage_gemm_mma(
    const float* __restrict__ Adst, const float* __restrict__ Agg,
    const float* __restrict__ Bt, const float* __restrict__ bias,
    float* __restrict__ out, int M, int K, int N_out, int relu)
{
    constexpr int NT = NPAD / 32;
    extern __shared__ float smem[];
    float* AsBase = smem;
    float* BsBase = smem + 2 * 128 * LDS_P;

    const uint32_t sb = smem_u32(smem);
    const uint32_t sb_b = sb + 2u * 128u * LDS_P * 4u;
    const int tid = threadIdx.x;
    const int wid = tid >> 5, lane = tid & 31;
    const int g = lane >> 2, tg = lane & 3;
    const int wm = wid & 1, wn = wid >> 1;
    const int m0 = blockIdx.x * 128;
    const int K2 = 2 * K;
    const int nc = K2 / 32;

    float acc[4][NT][4];
    #pragma unroll
    for (int m = 0; m < 4; m++)
        #pragma unroll
        for (int n = 0; n < NT; n++)
            #pragma unroll
            for (int j = 0; j < 4; j++) acc[m][n][j] = 0.f;

    auto issue = [&](int ic) {
        const int buf = ic & 1;
        const int kb_b = ic * 32;
        int kb = kb_b;
        const float* __restrict__ Ap = Adst;
        if (kb >= K) { Ap = Agg; kb -= K; }
        #pragma unroll
        for (int t = 0; t < 4; t++) {
            int idx = tid + t * 256;
            int r = idx >> 3, q = idx & 7;
            int gr = m0 + r;
            int grc = gr < M ? gr : (M - 1);
            const float* src = Ap + (size_t)grc * K + kb + q * 4;
            uint32_t dst = sb + (uint32_t)((buf * 128 + r) * LDS_P + q * 4) * 4u;
            cp16(dst, src, gr < M ? 16 : 0);
        }
        #pragma unroll
        for (int t = 0; t < NPAD / 32; t++) {
            int idx = tid + t * 256;
            int n = idx >> 3, q = idx & 7;
            const float* src = Bt + (size_t)n * K2 + kb_b + q * 4;
            uint32_t dst = sb_b + (uint32_t)((buf * NPAD + n) * LDS_P + q * 4) * 4u;
            cp16(dst, src, 16);
        }
        asm volatile("cp.async.commit_group;" ::: "memory");
    };

    issue(0);
    for (int ic = 0; ic < nc; ic++) {
        if (ic + 1 < nc) {
            issue(ic + 1);
            asm volatile("cp.async.wait_group 1;" ::: "memory");
        } else {
            asm volatile("cp.async.wait_group 0;" ::: "memory");
        }
        __syncthreads();

        const float* a_ = AsBase + (ic & 1) * 128 * LDS_P;
        const float* b_ = BsBase + (ic & 1) * NPAD * LDS_P;

        #pragma unroll
        for (int s = 0; s < 4; s++) {
            const int c = s * 8 + tg;
            uint32_t af[4][4];
            #pragma unroll
            for (int m = 0; m < 4; m++) {
                int r = wm * 64 + m * 16 + g;
                af[m][0] = f2tf32(a_[r * LDS_P + c]);
                af[m][1] = f2tf32(a_[(r + 8) * LDS_P + c]);
                af[m][2] = f2tf32(a_[r * LDS_P + c + 4]);
                af[m][3] = f2tf32(a_[(r + 8) * LDS_P + c + 4]);
            }
            uint32_t bf[NT][2];
            #pragma unroll
            for (int n = 0; n < NT; n++) {
                int nn = wn * (NPAD / 4) + n * 8 + g;
                bf[n][0] = f2tf32(b_[nn * LDS_P + c]);
                bf[n][1] = f2tf32(b_[nn * LDS_P + c + 4]);
            }
            #pragma unroll
            for (int m = 0; m < 4; m++)
                #pragma unroll
                for (int n = 0; n < NT; n++)
                    mma_tf32(acc[m][n], af[m], bf[n]);
        }
        __syncthreads();
    }

    #pragma unroll
    for (int m = 0; m < 4; m++) {
        const int r0 = m0 + wm * 64 + m * 16 + g;
        #pragma unroll
        for (int n = 0; n < NT; n++) {
            const int c0 = wn * (NPAD / 4) + n * 8 + tg * 2;
            #pragma unroll
            for (int i = 0; i < 2; i++) {
                const int r = r0 + i * 8;
                if (r >= M) continue;
                #pragma unroll
                for (int j = 0; j < 2; j++) {
                    const int cc = c0 + j;
                    if (cc >= N_out) continue;
                    float v = acc[m][n][i * 2 + j] + bias[cc];
                    if (relu) v = fmaxf(v, 0.f);
                    out[(size_t)r * N_out + cc] = v;
                }
            }
        }
    }
}

#define SMEM256 ((2 * 128 * LDS_P + 2 * 256 * LDS_P) * 4)
#define SMEM64  ((2 * 128 * LDS_P + 2 * 64 * LDS_P) * 4)

// ---------------- host orchestration ----------------
extern "C" void kernel_launch(void* const* d_in, const int* in_sizes, int n_in,
                              void* d_out, int out_size) {
    const float* x    = (const float*)d_in[0];
    const int*   src0 = (const int*)  d_in[1];
    const int*   dst0 = (const int*)  d_in[2];
    const int*   src1 = (const int*)  d_in[3];
    const int*   dst1 = (const int*)  d_in[4];
    const int*   src2 = (const int*)  d_in[5];
    const int*   dst2 = (const int*)  d_in[6];
    const float* Ws0  = (const float*)d_in[7];
    const float* Wn0  = (const float*)d_in[8];
    const float* b0   = (const float*)d_in[9];
    const float* Ws1  = (const float*)d_in[10];
    const float* Wn1  = (const float*)d_in[11];
    const float* b1   = (const float*)d_in[12];
    const float* Ws2  = (const float*)d_in[13];
    const float* Wn2  = (const float*)d_in[14];
    const float* b2   = (const float*)d_in[15];
    float* out = (float*)d_out;

    float *agg0, *h1, *agg1, *h2, *agg2, *bt0, *bt1, *bt2;
    int *rp0, *rp1, *rp2, *ei0, *ei1, *ei2;
    cudaGetSymbolAddress((void**)&agg0, g_agg0);
    cudaGetSymbolAddress((void**)&h1,   g_h1);
    cudaGetSymbolAddress((void**)&agg1, g_agg1);
    cudaGetSymbolAddress((void**)&h2,   g_h2);
    cudaGetSymbolAddress((void**)&agg2, g_agg2);
    cudaGetSymbolAddress((void**)&rp0, g_rp0);
    cudaGetSymbolAddress((void**)&rp1, g_rp1);
    cudaGetSymbolAddress((void**)&rp2, g_rp2);
    cudaGetSymbolAddress((void**)&ei0, g_eidx0);
    cudaGetSymbolAddress((void**)&ei1, g_eidx1);
    cudaGetSymbolAddress((void**)&ei2, g_eidx2);
    cudaGetSymbolAddress((void**)&bt0, g_Bt0);
    cudaGetSymbolAddress((void**)&bt1, g_Bt1);
    cudaGetSymbolAddress((void**)&bt2, g_Bt2);

    cudaFuncSetAttribute(sage_gemm_mma<256>,
                         cudaFuncAttributeMaxDynamicSharedMemorySize, SMEM256);
    cudaFuncSetAttribute(sage_gemm_mma<64>,
                         cudaFuncAttributeMaxDynamicSharedMemorySize, SMEM64);

    const int TB = 256;
    const int BT_TOT = 65536 + 131072 + 32768;

    // ---- batched Bt build + cnt zero (one launch; must precede hist) ----
    build_bt_zero_kernel<<<(BT_TOT + TB - 1) / TB, TB>>>(Ws0, Wn0, Ws1, Wn1, Ws2, Wn2);

    // ---- batched CSR build for ALL layers ----
    hist_all_kernel<<<(ETOT + TB - 1) / TB, TB>>>(dst0, dst1, dst2);
    scan1_all_kernel<<<NBT, TB>>>();
    scan23_all_kernel<<<NBT, TB>>>();
    fillidx_all_kernel<<<(ETOT + TB - 1) / TB, TB>>>(src0, dst0, src1, dst1, src2, dst2);

    // ---- layer 0: x[300000,128] -> h1[100000,256], relu ----
    gather_agg_kernel<1><<<(NDST0 * 32 + TB - 1) / TB, TB>>>(
        (const float4*)x, rp0, ei0, (float4*)agg0, NDST0);
    sage_gemm_mma<256><<<(NDST0 + 127) / 128, 256, SMEM256>>>(
        x, agg0, bt0, b0, h1, NDST0, D_IN, 256, 1);

    // ---- layer 1: h1[100000,256] -> h2[20000,256], relu ----
    gather_agg_kernel<2><<<(NDST1 * 32 + TB - 1) / TB, TB>>>(
        (const float4*)h1, rp1, ei1, (float4*)agg1, NDST1);
    sage_gemm_mma<256><<<(NDST1 + 127) / 128, 256, SMEM256>>>(
        h1, agg1, bt1, b1, h2, NDST1, D_H, 256, 1);

    // ---- layer 2: h2[20000,256] -> out[4096,47], no relu ----
    gather_agg_kernel<2><<<(NDST2 * 32 + TB - 1) / TB, TB>>>(
        (const float4*)h2, rp2, ei2, (float4*)agg2, NDST2);
    sage_gemm_mma<64><<<(NDST2 + 127) / 128, 256, SMEM64>>>(
        h2, agg2, bt2, b2, out, NDST2, D_H, 47, 0);
}

// round 16
// speedup vs baseline: 1.7505x; 1.3109x over previous
#include <cuda_runtime.h>
#include <cuda_fp16.h>
#include <cstdint>

// ---------------- problem constants ----------------
#define NDST0  100000
#define NDST1  20000
#define NDST2  4096
#define NE0    1000000
#define NE1    300000
#define NE2    61440
#define D_IN   128
#define D_H    256
#define D_OUT  47

#define NB0 ((NDST0 + 255) / 256)   // 391
#define NB1 ((NDST1 + 255) / 256)   // 79
#define NB2 ((NDST2 + 255) / 256)   // 16
#define NBT (NB0 + NB1 + NB2)       // 486
#define ETOT (NE0 + NE1 + NE2)      // 1361440
#define NTOT (NDST0 + NDST1 + NDST2)

// ---------------- scratch (device globals: allocation-free) ----------------
__device__ __half g_xh[(size_t)300000 * D_IN];       // fp16 copy of x
__device__ __half g_agg0h[(size_t)NDST0 * D_IN];
__device__ __half g_h1h[(size_t)NDST0 * D_H];
__device__ __half g_agg1h[(size_t)NDST1 * D_H];
__device__ __half g_h2h[(size_t)NDST1 * D_H];
__device__ __half g_agg2h[(size_t)NDST2 * D_H];
// per-layer CSR buffers
__device__ int g_cnt0[NDST0];
__device__ int g_cnt1[NDST1];
__device__ int g_cnt2[NDST2];
__device__ int g_rp0[NDST0 + 1];
__device__ int g_rp1[NDST1 + 1];
__device__ int g_rp2[NDST2 + 1];
__device__ int g_cur0[NDST0];
__device__ int g_cur1[NDST1];
__device__ int g_cur2[NDST2];
__device__ int g_eidx0[NE0];
__device__ int g_eidx1[NE1];
__device__ int g_eidx2[NE2];
__device__ int g_bsum0[NB0];
__device__ int g_bsum1[NB1];
__device__ int g_bsum2[NB2];
// transposed/concat weights in fp16: Bt[n][k2] = (k2<K ? Ws[k2][n] : Wn[k2-K][n])
__device__ __half g_Bt0h[(size_t)256 * 256];
__device__ __half g_Bt1h[(size_t)256 * 512];
__device__ __half g_Bt2h[(size_t)64 * 512];

// ---------------- helpers ----------------
__device__ __forceinline__ uint32_t smem_u32(const void* p) {
    uint32_t a;
    asm("{ .reg .u64 t; cvta.to.shared.u64 t, %1; cvt.u32.u64 %0, t; }"
        : "=r"(a) : "l"(p));
    return a;
}

__device__ __forceinline__ void cp16(uint32_t dst, const void* src, int sz) {
    asm volatile("cp.async.cg.shared.global [%0], [%1], 16, %2;"
                 :: "r"(dst), "l"(src), "r"(sz));
}

__device__ __forceinline__ void mma_f16(float* c, const uint32_t* a, const uint32_t* b) {
    asm volatile(
        "mma.sync.aligned.m16n8k16.row.col.f32.f16.f16.f32 "
        "{%0,%1,%2,%3}, {%4,%5,%6,%7}, {%8,%9}, {%0,%1,%2,%3};"
        : "+f"(c[0]), "+f"(c[1]), "+f"(c[2]), "+f"(c[3])
        : "r"(a[0]), "r"(a[1]), "r"(a[2]), "r"(a[3]), "r"(b[0]), "r"(b[1]));
}

// ---------------- x -> fp16 convert ----------------
__global__ void cvt_x_kernel(const float4* __restrict__ x, uint2* __restrict__ xh,
                             long long n4) {
    long long i = (long long)blockIdx.x * blockDim.x + threadIdx.x;
    long long stride = (long long)gridDim.x * blockDim.x;
    for (; i < n4; i += stride) {
        float4 f = x[i];
        __half2 h0 = __floats2half2_rn(f.x, f.y);
        __half2 h1 = __floats2half2_rn(f.z, f.w);
        uint2 u;
        u.x = *reinterpret_cast<uint32_t*>(&h0);
        u.y = *reinterpret_cast<uint32_t*>(&h1);
        xh[i] = u;
    }
}

// ---------------- batched Bt build (fp16) + cnt zero (one launch) ----------------
__global__ void build_bt_zero_kernel(const float* __restrict__ Ws0, const float* __restrict__ Wn0,
                                     const float* __restrict__ Ws1, const float* __restrict__ Wn1,
                                     const float* __restrict__ Ws2, const float* __restrict__ Wn2) {
    long long i = (long long)blockIdx.x * blockDim.x + threadIdx.x;
    if (i < NDST0) g_cnt0[i] = 0;
    else if (i < NDST0 + NDST1) g_cnt1[i - NDST0] = 0;
    else if (i < NTOT) g_cnt2[i - NDST0 - NDST1] = 0;

    if (i >= 65536 + 131072 + 32768) return;
    const float *Ws, *Wn; __half* Bt; int K, N_out; long long j;
    if (i < 65536)               { Ws = Ws0; Wn = Wn0; Bt = g_Bt0h; K = 128; N_out = 256; j = i; }
    else if (i < 65536 + 131072) { Ws = Ws1; Wn = Wn1; Bt = g_Bt1h; K = 256; N_out = 256; j = i - 65536; }
    else                         { Ws = Ws2; Wn = Wn2; Bt = g_Bt2h; K = 256; N_out = 47;  j = i - 65536 - 131072; }
    int K2 = 2 * K;
    int n = (int)(j / K2);
    int k2 = (int)(j % K2);
    float v = 0.f;
    if (n < N_out)
        v = (k2 < K) ? Ws[(size_t)k2 * N_out + n] : Wn[(size_t)(k2 - K) * N_out + n];
    Bt[j] = __float2half_rn(v);
}

// ---------------- batched CSR build (R14-proven) ----------------
__global__ void hist_all_kernel(const int* __restrict__ d0, const int* __restrict__ d1,
                                const int* __restrict__ d2) {
    int i = blockIdx.x * blockDim.x + threadIdx.x;
    if (i < NE0) atomicAdd(&g_cnt0[d0[i]], 1);
    else if (i < NE0 + NE1) atomicAdd(&g_cnt1[d1[i - NE0]], 1);
    else if (i < ETOT) atomicAdd(&g_cnt2[d2[i - NE0 - NE1]], 1);
}

__global__ void scan1_all_kernel() {
    const int* cnt; int* bsum; int n; int lb;
    int b = blockIdx.x;
    if (b < NB0)            { cnt = g_cnt0; bsum = g_bsum0; n = NDST0; lb = b; }
    else if (b < NB0 + NB1) { cnt = g_cnt1; bsum = g_bsum1; n = NDST1; lb = b - NB0; }
    else                    { cnt = g_cnt2; bsum = g_bsum2; n = NDST2; lb = b - NB0 - NB1; }
    __shared__ int s[8];
    int i = lb * 256 + threadIdx.x;
    int v = (i < n) ? cnt[i] : 0;
    #pragma unroll
    for (int o = 16; o; o >>= 1) v += __shfl_down_sync(~0u, v, o);
    if ((threadIdx.x & 31) == 0) s[threadIdx.x >> 5] = v;
    __syncthreads();
    if (threadIdx.x < 8) {
        int x = s[threadIdx.x];
        #pragma unroll
        for (int o = 4; o; o >>= 1) x += __shfl_down_sync(0xff, x, o);
        if (threadIdx.x == 0) bsum[lb] = x;
    }
}

__global__ void scan23_all_kernel() {
    const int* cnt; const int* bsum; int* rowptr; int* cur; int n; int E; int lb;
    int b = blockIdx.x;
    if (b < NB0)            { cnt = g_cnt0; bsum = g_bsum0; rowptr = g_rp0; cur = g_cur0;
                              n = NDST0; E = NE0; lb = b; }
    else if (b < NB0 + NB1) { cnt = g_cnt1; bsum = g_bsum1; rowptr = g_rp1; cur = g_cur1;
                              n = NDST1; E = NE1; lb = b - NB0; }
    else                    { cnt = g_cnt2; bsum = g_bsum2; rowptr = g_rp2; cur = g_cur2;
                              n = NDST2; E = NE2; lb = b - NB0 - NB1; }
    __shared__ int s[256];
    __shared__ int off;
    int t = threadIdx.x;
    int i = lb * 256 + t;
    int v = (i < n) ? cnt[i] : 0;
    s[t] = v;
    if (t < 32) {
        int sum = 0;
        for (int k = t; k < lb; k += 32) sum += bsum[k];
        #pragma unroll
        for (int o = 16; o; o >>= 1) sum += __shfl_down_sync(~0u, sum, o);
        if (t == 0) off = sum;
    }
    __syncthreads();
    for (int o = 1; o < 256; o <<= 1) {
        int u = (t >= o) ? s[t - o] : 0;
        __syncthreads();
        s[t] += u;
        __syncthreads();
    }
    int ex = s[t] - v + off;
    if (i < n) { rowptr[i] = ex; cur[i] = ex; }
    if (i == 0) rowptr[n] = E;
}

__global__ void fillidx_all_kernel(const int* __restrict__ s0, const int* __restrict__ d0,
                                   const int* __restrict__ s1, const int* __restrict__ d1,
                                   const int* __restrict__ s2, const int* __restrict__ d2) {
    int i = blockIdx.x * blockDim.x + threadIdx.x;
    if (i < NE0) {
        int p = atomicAdd(&g_cur0[d0[i]], 1);
        g_eidx0[p] = s0[i];
    } else if (i < NE0 + NE1) {
        int j = i - NE0;
        int p = atomicAdd(&g_cur1[d1[j]], 1);
        g_eidx1[p] = s1[j];
    } else if (i < ETOT) {
        int j = i - NE0 - NE1;
        int p = atomicAdd(&g_cur2[d2[j]], 1);
        g_eidx2[p] = s2[j];
    }
}

// ---------------- fp16 gather: one warp per dst row, unroll-2 (proven shape) ----------------
// H2 = half2's per lane: 2 for d=128 rows, 4 for d=256 rows.
template<int H2>
__global__ __launch_bounds__(256) void gather_h_kernel(
    const __half* __restrict__ feat, const int* __restrict__ rowptr,
    const int* __restrict__ eidx, __half* __restrict__ agg, int n_dst)
{
    int w = (blockIdx.x * blockDim.x + threadIdx.x) >> 5;
    if (w >= n_dst) return;
    int lane = threadIdx.x & 31;
    const int rowu = H2 * 32;                      // uints (half2) per row
    const uint32_t* f = reinterpret_cast<const uint32_t*>(feat);
    int beg = rowptr[w], end = rowptr[w + 1];

    float2 acc[H2];
    #pragma unroll
    for (int v = 0; v < H2; v++) acc[v] = make_float2(0.f, 0.f);

    int j = beg;
    for (; j + 1 < end; j += 2) {
        int s0 = eidx[j], s1 = eidx[j + 1];
        uint32_t u0[H2], u1[H2];
        const uint32_t* p0 = f + (size_t)s0 * rowu + lane * H2;
        const uint32_t* p1 = f + (size_t)s1 * rowu + lane * H2;
        #pragma unroll
        for (int v = 0; v < H2; v++) { u0[v] = p0[v]; u1[v] = p1[v]; }
        #pragma unroll
        for (int v = 0; v < H2; v++) {
            float2 a = __half22float2(*reinterpret_cast<__half2*>(&u0[v]));
            float2 b = __half22float2(*reinterpret_cast<__half2*>(&u1[v]));
            acc[v].x += a.x + b.x;
            acc[v].y += a.y + b.y;
        }
    }
    if (j < end) {
        int s0 = eidx[j];
        const uint32_t* p0 = f + (size_t)s0 * rowu + lane * H2;
        #pragma unroll
        for (int v = 0; v < H2; v++) {
            uint32_t u = p0[v];
            float2 a = __half22float2(*reinterpret_cast<__half2*>(&u));
            acc[v].x += a.x;
            acc[v].y += a.y;
        }
    }

    float inv = 1.0f / (float)max(end - beg, 1);
    uint32_t* o = reinterpret_cast<uint32_t*>(agg) + (size_t)w * rowu + lane * H2;
    #pragma unroll
    for (int v = 0; v < H2; v++) {
        __half2 hv = __floats2half2_rn(acc[v].x * inv, acc[v].y * inv);
        o[v] = *reinterpret_cast<uint32_t*>(&hv);
    }
}

// ---------------- fp16 mma.sync m16n8k16 fused SAGE GEMM ----------------
// Same tile structure as the proven tf32 kernel: 256 threads, 2x4 warp grid,
// 128 x NPAD output tile, K'=2K concat, 32-k chunks double-buffered via cp.async.
// SMEM stride 40 halves (80B): fragment LDS conflict-free (20g+tg covers 32 banks).
#define STRH 40

template<int NPAD, int OUTH>
__global__ __launch_bounds__(256, 1) void sage_gemm_h(
    const __half* __restrict__ Adst, const __half* __restrict__ Agg,
    const __half* __restrict__ Bt, const float* __restrict__ bias,
    void* __restrict__ outv, int M, int K, int N_out, int relu)
{
    constexpr int NT = NPAD / 32;
    extern __shared__ __half smh[];
    __half* AsBase = smh;                          // [2][128][STRH]
    __half* BsBase = smh + 2 * 128 * STRH;         // [2][NPAD][STRH]

    const uint32_t sb_a = smem_u32(AsBase);
    const uint32_t sb_b = smem_u32(BsBase);
    const int tid = threadIdx.x;
    const int wid = tid >> 5, lane = tid & 31;
    const int g = lane >> 2, tg = lane & 3;
    const int wm = wid & 1, wn = wid >> 1;
    const int m0 = blockIdx.x * 128;
    const int K2 = 2 * K;
    const int nc = K2 / 32;

    float acc[4][NT][4];
    #pragma unroll
    for (int m = 0; m < 4; m++)
        #pragma unroll
        for (int n = 0; n < NT; n++)
            #pragma unroll
            for (int j = 0; j < 4; j++) acc[m][n][j] = 0.f;

    auto issue = [&](int ic) {
        const int buf = ic & 1;
        const int kb_b = ic * 32;                  // half index in concat K2
        int kb = kb_b;
        const __half* __restrict__ Ap = Adst;
        if (kb >= K) { Ap = Agg; kb -= K; }
        // A chunk: 128 rows x 32 halves (64B) = 4 x 16B per row, 512 cp16
        #pragma unroll
        for (int t = 0; t < 2; t++) {
            int idx = tid + t * 256;
            int r = idx >> 2, q = idx & 3;
            int gr = m0 + r;
            int grc = gr < M ? gr : (M - 1);
            const __half* src = Ap + (size_t)grc * K + kb + q * 8;
            uint32_t dst = sb_a + (uint32_t)((buf * 128 + r) * STRH + q * 8) * 2u;
            cp16(dst, src, gr < M ? 16 : 0);
        }
        // B chunk: NPAD rows x 4 x 16B
        #pragma unroll
        for (int t = 0; t < NPAD / 64; t++) {
            int idx = tid + t * 256;
            int n = idx >> 2, q = idx & 3;
            const __half* src = Bt + (size_t)n * K2 + kb_b + q * 8;
            uint32_t dst = sb_b + (uint32_t)((buf * NPAD + n) * STRH + q * 8) * 2u;
            cp16(dst, src, 16);
        }
        asm volatile("cp.async.commit_group;" ::: "memory");
    };

    issue(0);
    for (int ic = 0; ic < nc; ic++) {
        if (ic + 1 < nc) {
            issue(ic + 1);
            asm volatile("cp.async.wait_group 1;" ::: "memory");
        } else {
            asm volatile("cp.async.wait_group 0;" ::: "memory");
        }
        __syncthreads();

        const __half* a_ = AsBase + (ic & 1) * 128 * STRH;
        const __half* b_ = BsBase + (ic & 1) * NPAD * STRH;

        #pragma unroll
        for (int s = 0; s < 2; s++) {              // two k16 steps per 32-k chunk
            const int c2 = s * 16 + 2 * tg;        // half column
            uint32_t af[4][4];
            #pragma unroll
            for (int m = 0; m < 4; m++) {
                int r = wm * 64 + m * 16 + g;
                af[m][0] = *reinterpret_cast<const uint32_t*>(a_ + r * STRH + c2);
                af[m][1] = *reinterpret_cast<const uint32_t*>(a_ + (r + 8) * STRH + c2);
                af[m][2] = *reinterpret_cast<const uint32_t*>(a_ + r * STRH + c2 + 8);
                af[m][3] = *reinterpret_cast<const uint32_t*>(a_ + (r + 8) * STRH + c2 + 8);
            }
            uint32_t bf[NT][2];
            #pragma unroll
            for (int n = 0; n < NT; n++) {
                int nn = wn * (NPAD / 4) + n * 8 + g;
                bf[n][0] = *reinterpret_cast<const uint32_t*>(b_ + nn * STRH + c2);
                bf[n][1] = *reinterpret_cast<const uint32_t*>(b_ + nn * STRH + c2 + 8);
            }
            #pragma unroll
            for (int m = 0; m < 4; m++)
                #pragma unroll
                for (int n = 0; n < NT; n++)
                    mma_f16(acc[m][n], af[m], bf[n]);
        }
        __syncthreads();
    }

    // epilogue: bias + optional relu; fp16 (half2) or fp32 scalar output
    #pragma unroll
    for (int m = 0; m < 4; m++) {
        const int r0 = m0 + wm * 64 + m * 16 + g;
        #pragma unroll
        for (int n = 0; n < NT; n++) {
            const int c0 = wn * (NPAD / 4) + n * 8 + tg * 2;
            #pragma unroll
            for (int i = 0; i < 2; i++) {
                const int r = r0 + i * 8;
                if (r >= M) continue;
                float v0 = acc[m][n][i * 2 + 0] + bias[c0 < N_out ? c0 : 0];
                float v1 = acc[m][n][i * 2 + 1] + bias[(c0 + 1) < N_out ? (c0 + 1) : 0];
                if (relu) { v0 = fmaxf(v0, 0.f); v1 = fmaxf(v1, 0.f); }
                if (OUTH) {
                    __half2 hv = __floats2half2_rn(v0, v1);
                    *reinterpret_cast<__half2*>(
                        (__half*)outv + (size_t)r * N_out + c0) = hv;
                } else {
                    float* outp = (float*)outv;
                    if (c0 < N_out)     outp[(size_t)r * N_out + c0] = v0;
                    if (c0 + 1 < N_out) outp[(size_t)r * N_out + c0 + 1] = v1;
                }
            }
        }
    }
}

#define SMEMH256 ((2 * 128 * STRH + 2 * 256 * STRH) * 2)   // 61440 B
#define SMEMH64  ((2 * 128 * STRH + 2 * 64 * STRH) * 2)    // 30720 B

// ---------------- host orchestration ----------------
extern "C" void kernel_launch(void* const* d_in, const int* in_sizes, int n_in,
                              void* d_out, int out_size) {
    const float* x    = (const float*)d_in[0];
    const int*   src0 = (const int*)  d_in[1];
    const int*   dst0 = (const int*)  d_in[2];
    const int*   src1 = (const int*)  d_in[3];
    const int*   dst1 = (const int*)  d_in[4];
    const int*   src2 = (const int*)  d_in[5];
    const int*   dst2 = (const int*)  d_in[6];
    const float* Ws0  = (const float*)d_in[7];
    const float* Wn0  = (const float*)d_in[8];
    const float* b0   = (const float*)d_in[9];
    const float* Ws1  = (const float*)d_in[10];
    const float* Wn1  = (const float*)d_in[11];
    const float* b1   = (const float*)d_in[12];
    const float* Ws2  = (const float*)d_in[13];
    const float* Wn2  = (const float*)d_in[14];
    const float* b2   = (const float*)d_in[15];
    float* out = (float*)d_out;

    __half *xh, *agg0h, *h1h, *agg1h, *h2h, *agg2h, *bt0h, *bt1h, *bt2h;
    int *rp0, *rp1, *rp2, *ei0, *ei1, *ei2;
    cudaGetSymbolAddress((void**)&xh,    g_xh);
    cudaGetSymbolAddress((void**)&agg0h, g_agg0h);
    cudaGetSymbolAddress((void**)&h1h,   g_h1h);
    cudaGetSymbolAddress((void**)&agg1h, g_agg1h);
    cudaGetSymbolAddress((void**)&h2h,   g_h2h);
    cudaGetSymbolAddress((void**)&agg2h, g_agg2h);
    cudaGetSymbolAddress((void**)&rp0, g_rp0);
    cudaGetSymbolAddress((void**)&rp1, g_rp1);
    cudaGetSymbolAddress((void**)&rp2, g_rp2);
    cudaGetSymbolAddress((void**)&ei0, g_eidx0);
    cudaGetSymbolAddress((void**)&ei1, g_eidx1);
    cudaGetSymbolAddress((void**)&ei2, g_eidx2);
    cudaGetSymbolAddress((void**)&bt0h, g_Bt0h);
    cudaGetSymbolAddress((void**)&bt1h, g_Bt1h);
    cudaGetSymbolAddress((void**)&bt2h, g_Bt2h);

    cudaFuncSetAttribute(sage_gemm_h<256, 1>,
                         cudaFuncAttributeMaxDynamicSharedMemorySize, SMEMH256);
    cudaFuncSetAttribute(sage_gemm_h<64, 0>,
                         cudaFuncAttributeMaxDynamicSharedMemorySize, SMEMH64);

    const int TB = 256;
    const int BT_TOT = 65536 + 131072 + 32768;
    const long long XN4 = (long long)300000 * D_IN / 4;   // 9.6M float4

    // ---- batched Bt(fp16) build + cnt zero ----
    build_bt_zero_kernel<<<(BT_TOT + TB - 1) / TB, TB>>>(Ws0, Wn0, Ws1, Wn1, Ws2, Wn2);

    // ---- x -> fp16 ----
    {
        long long g = (XN4 + TB - 1) / TB;
        if (g > 118784) g = 118784;
        cvt_x_kernel<<<(int)g, TB>>>((const float4*)x, (uint2*)xh, XN4);
    }

    // ---- batched CSR build ----
    hist_all_kernel<<<(ETOT + TB - 1) / TB, TB>>>(dst0, dst1, dst2);
    scan1_all_kernel<<<NBT, TB>>>();
    scan23_all_kernel<<<NBT, TB>>>();
    fillidx_all_kernel<<<(ETOT + TB - 1) / TB, TB>>>(src0, dst0, src1, dst1, src2, dst2);

    // ---- layer 0: x_h[300000,128] -> h1_h[100000,256], relu ----
    gather_h_kernel<2><<<(NDST0 * 32 + TB - 1) / TB, TB>>>(
        xh, rp0, ei0, agg0h, NDST0);
    sage_gemm_h<256, 1><<<(NDST0 + 127) / 128, 256, SMEMH256>>>(
        xh, agg0h, bt0h, b0, h1h, NDST0, D_IN, 256, 1);

    // ---- layer 1: h1_h -> h2_h[20000,256], relu ----
    gather_h_kernel<4><<<(NDST1 * 32 + TB - 1) / TB, TB>>>(
        h1h, rp1, ei1, agg1h, NDST1);
    sage_gemm_h<256, 1><<<(NDST1 + 127) / 128, 256, SMEMH256>>>(
        h1h, agg1h, bt1h, b1, h2h, NDST1, D_H, 256, 1);

    // ---- layer 2: h2_h -> out[4096,47] fp32, no relu ----
    gather_h_kernel<4><<<(NDST2 * 32 + TB - 1) / TB, TB>>>(
        h2h, rp2, ei2, agg2h, NDST2);
    sage_gemm_h<64, 0><<<(NDST2 + 127) / 128, 256, SMEMH64>>>(
        h2h, agg2h, bt2h, b2, out, NDST2, D_H, 47, 0);
}

// round 17
// speedup vs baseline: 1.7632x; 1.0072x over previous
#include <cuda_runtime.h>
#include <cuda_fp16.h>
#include <cstdint>

// ---------------- problem constants ----------------
#define NDST0  100000
#define NDST1  20000
#define NDST2  4096
#define NE0    1000000
#define NE1    300000
#define NE2    61440
#define D_IN   128
#define D_H    256
#define D_OUT  47

#define NB0 ((NDST0 + 255) / 256)   // 391
#define NB1 ((NDST1 + 255) / 256)   // 79
#define NB2 ((NDST2 + 255) / 256)   // 16
#define NBT (NB0 + NB1 + NB2)       // 486
#define ETOT (NE0 + NE1 + NE2)      // 1361440
#define NTOT (NDST0 + NDST1 + NDST2)

// ---------------- scratch (device globals: allocation-free) ----------------
__device__ __half g_xh[(size_t)300000 * D_IN];       // fp16 copy of x
__device__ __half g_agg0h[(size_t)NDST0 * D_IN];
__device__ __half g_h1h[(size_t)NDST0 * D_H];
__device__ __half g_agg1h[(size_t)NDST1 * D_H];
__device__ __half g_h2h[(size_t)NDST1 * D_H];
__device__ __half g_agg2h[(size_t)NDST2 * D_H];
// per-layer CSR buffers
__device__ int g_cnt0[NDST0];
__device__ int g_cnt1[NDST1];
__device__ int g_cnt2[NDST2];
__device__ int g_rp0[NDST0 + 1];
__device__ int g_rp1[NDST1 + 1];
__device__ int g_rp2[NDST2 + 1];
__device__ int g_cur0[NDST0];
__device__ int g_cur1[NDST1];
__device__ int g_cur2[NDST2];
__device__ int g_eidx0[NE0];
__device__ int g_eidx1[NE1];
__device__ int g_eidx2[NE2];
__device__ int g_bsum0[NB0];
__device__ int g_bsum1[NB1];
__device__ int g_bsum2[NB2];
// transposed/concat weights in fp16: Bt[n][k2] = (k2<K ? Ws[k2][n] : Wn[k2-K][n])
__device__ __half g_Bt0h[(size_t)256 * 256];
__device__ __half g_Bt1h[(size_t)256 * 512];
__device__ __half g_Bt2h[(size_t)64 * 512];

// ---------------- helpers ----------------
__device__ __forceinline__ uint32_t smem_u32(const void* p) {
    uint32_t a;
    asm("{ .reg .u64 t; cvta.to.shared.u64 t, %1; cvt.u32.u64 %0, t; }"
        : "=r"(a) : "l"(p));
    return a;
}

__device__ __forceinline__ void cp16(uint32_t dst, const void* src, int sz) {
    asm volatile("cp.async.cg.shared.global [%0], [%1], 16, %2;"
                 :: "r"(dst), "l"(src), "r"(sz));
}

__device__ __forceinline__ void mma_f16(float* c, const uint32_t* a, const uint32_t* b) {
    asm volatile(
        "mma.sync.aligned.m16n8k16.row.col.f32.f16.f16.f32 "
        "{%0,%1,%2,%3}, {%4,%5,%6,%7}, {%8,%9}, {%0,%1,%2,%3};"
        : "+f"(c[0]), "+f"(c[1]), "+f"(c[2]), "+f"(c[3])
        : "r"(a[0]), "r"(a[1]), "r"(a[2]), "r"(a[3]), "r"(b[0]), "r"(b[1]));
}

#define LDSM_X4(r0, r1, r2, r3, addr) \
    asm volatile("ldmatrix.sync.aligned.m8n8.x4.shared.b16 {%0,%1,%2,%3}, [%4];" \
                 : "=r"(r0), "=r"(r1), "=r"(r2), "=r"(r3) : "r"(addr))

// ---------------- x -> fp16 convert ----------------
__global__ void cvt_x_kernel(const float4* __restrict__ x, uint2* __restrict__ xh,
                             long long n4) {
    long long i = (long long)blockIdx.x * blockDim.x + threadIdx.x;
    long long stride = (long long)gridDim.x * blockDim.x;
    for (; i < n4; i += stride) {
        float4 f = x[i];
        __half2 h0 = __floats2half2_rn(f.x, f.y);
        __half2 h1 = __floats2half2_rn(f.z, f.w);
        uint2 u;
        u.x = *reinterpret_cast<uint32_t*>(&h0);
        u.y = *reinterpret_cast<uint32_t*>(&h1);
        xh[i] = u;
    }
}

// ---------------- batched Bt build (fp16) + cnt zero (one launch) ----------------
__global__ void build_bt_zero_kernel(const float* __restrict__ Ws0, const float* __restrict__ Wn0,
                                     const float* __restrict__ Ws1, const float* __restrict__ Wn1,
                                     const float* __restrict__ Ws2, const float* __restrict__ Wn2) {
    long long i = (long long)blockIdx.x * blockDim.x + threadIdx.x;
    if (i < NDST0) g_cnt0[i] = 0;
    else if (i < NDST0 + NDST1) g_cnt1[i - NDST0] = 0;
    else if (i < NTOT) g_cnt2[i - NDST0 - NDST1] = 0;

    if (i >= 65536 + 131072 + 32768) return;
    const float *Ws, *Wn; __half* Bt; int K, N_out; long long j;
    if (i < 65536)               { Ws = Ws0; Wn = Wn0; Bt = g_Bt0h; K = 128; N_out = 256; j = i; }
    else if (i < 65536 + 131072) { Ws = Ws1; Wn = Wn1; Bt = g_Bt1h; K = 256; N_out = 256; j = i - 65536; }
    else                         { Ws = Ws2; Wn = Wn2; Bt = g_Bt2h; K = 256; N_out = 47;  j = i - 65536 - 131072; }
    int K2 = 2 * K;
    int n = (int)(j / K2);
    int k2 = (int)(j % K2);
    float v = 0.f;
    if (n < N_out)
        v = (k2 < K) ? Ws[(size_t)k2 * N_out + n] : Wn[(size_t)(k2 - K) * N_out + n];
    Bt[j] = __float2half_rn(v);
}

// ---------------- batched CSR build (R14-proven) ----------------
__global__ void hist_all_kernel(const int* __restrict__ d0, const int* __restrict__ d1,
                                const int* __restrict__ d2) {
    int i = blockIdx.x * blockDim.x + threadIdx.x;
    if (i < NE0) atomicAdd(&g_cnt0[d0[i]], 1);
    else if (i < NE0 + NE1) atomicAdd(&g_cnt1[d1[i - NE0]], 1);
    else if (i < ETOT) atomicAdd(&g_cnt2[d2[i - NE0 - NE1]], 1);
}

__global__ void scan1_all_kernel() {
    const int* cnt; int* bsum; int n; int lb;
    int b = blockIdx.x;
    if (b < NB0)            { cnt = g_cnt0; bsum = g_bsum0; n = NDST0; lb = b; }
    else if (b < NB0 + NB1) { cnt = g_cnt1; bsum = g_bsum1; n = NDST1; lb = b - NB0; }
    else                    { cnt = g_cnt2; bsum = g_bsum2; n = NDST2; lb = b - NB0 - NB1; }
    __shared__ int s[8];
    int i = lb * 256 + threadIdx.x;
    int v = (i < n) ? cnt[i] : 0;
    #pragma unroll
    for (int o = 16; o; o >>= 1) v += __shfl_down_sync(~0u, v, o);
    if ((threadIdx.x & 31) == 0) s[threadIdx.x >> 5] = v;
    __syncthreads();
    if (threadIdx.x < 8) {
        int x = s[threadIdx.x];
        #pragma unroll
        for (int o = 4; o; o >>= 1) x += __shfl_down_sync(0xff, x, o);
        if (threadIdx.x == 0) bsum[lb] = x;
    }
}

__global__ void scan23_all_kernel() {
    const int* cnt; const int* bsum; int* rowptr; int* cur; int n; int E; int lb;
    int b = blockIdx.x;
    if (b < NB0)            { cnt = g_cnt0; bsum = g_bsum0; rowptr = g_rp0; cur = g_cur0;
                              n = NDST0; E = NE0; lb = b; }
    else if (b < NB0 + NB1) { cnt = g_cnt1; bsum = g_bsum1; rowptr = g_rp1; cur = g_cur1;
                              n = NDST1; E = NE1; lb = b - NB0; }
    else                    { cnt = g_cnt2; bsum = g_bsum2; rowptr = g_rp2; cur = g_cur2;
                              n = NDST2; E = NE2; lb = b - NB0 - NB1; }
    __shared__ int s[256];
    __shared__ int off;
    int t = threadIdx.x;
    int i = lb * 256 + t;
    int v = (i < n) ? cnt[i] : 0;
    s[t] = v;
    if (t < 32) {
        int sum = 0;
        for (int k = t; k < lb; k += 32) sum += bsum[k];
        #pragma unroll
        for (int o = 16; o; o >>= 1) sum += __shfl_down_sync(~0u, sum, o);
        if (t == 0) off = sum;
    }
    __syncthreads();
    for (int o = 1; o < 256; o <<= 1) {
        int u = (t >= o) ? s[t - o] : 0;
        __syncthreads();
        s[t] += u;
        __syncthreads();
    }
    int ex = s[t] - v + off;
    if (i < n) { rowptr[i] = ex; cur[i] = ex; }
    if (i == 0) rowptr[n] = E;
}

__global__ void fillidx_all_kernel(const int* __restrict__ s0, const int* __restrict__ d0,
                                   const int* __restrict__ s1, const int* __restrict__ d1,
                                   const int* __restrict__ s2, const int* __restrict__ d2) {
    int i = blockIdx.x * blockDim.x + threadIdx.x;
    if (i < NE0) {
        int p = atomicAdd(&g_cur0[d0[i]], 1);
        g_eidx0[p] = s0[i];
    } else if (i < NE0 + NE1) {
        int j = i - NE0;
        int p = atomicAdd(&g_cur1[d1[j]], 1);
        g_eidx1[p] = s1[j];
    } else if (i < ETOT) {
        int j = i - NE0 - NE1;
        int p = atomicAdd(&g_cur2[d2[j]], 1);
        g_eidx2[p] = s2[j];
    }
}

// ---------------- fp16 gather: one warp per dst row, unroll-2 (proven shape) ----------------
template<int H2>
__global__ __launch_bounds__(256) void gather_h_kernel(
    const __half* __restrict__ feat, const int* __restrict__ rowptr,
    const int* __restrict__ eidx, __half* __restrict__ agg, int n_dst)
{
    int w = (blockIdx.x * blockDim.x + threadIdx.x) >> 5;
    if (w >= n_dst) return;
    int lane = threadIdx.x & 31;
    const int rowu = H2 * 32;
    const uint32_t* f = reinterpret_cast<const uint32_t*>(feat);
    int beg = rowptr[w], end = rowptr[w + 1];

    float2 acc[H2];
    #pragma unroll
    for (int v = 0; v < H2; v++) acc[v] = make_float2(0.f, 0.f);

    int j = beg;
    for (; j + 1 < end; j += 2) {
        int s0 = eidx[j], s1 = eidx[j + 1];
        uint32_t u0[H2], u1[H2];
        const uint32_t* p0 = f + (size_t)s0 * rowu + lane * H2;
        const uint32_t* p1 = f + (size_t)s1 * rowu + lane * H2;
        #pragma unroll
        for (int v = 0; v < H2; v++) { u0[v] = p0[v]; u1[v] = p1[v]; }
        #pragma unroll
        for (int v = 0; v < H2; v++) {
            float2 a = __half22float2(*reinterpret_cast<__half2*>(&u0[v]));
            float2 b = __half22float2(*reinterpret_cast<__half2*>(&u1[v]));
            acc[v].x += a.x + b.x;
            acc[v].y += a.y + b.y;
        }
    }
    if (j < end) {
        int s0 = eidx[j];
        const uint32_t* p0 = f + (size_t)s0 * rowu + lane * H2;
        #pragma unroll
        for (int v = 0; v < H2; v++) {
            uint32_t u = p0[v];
            float2 a = __half22float2(*reinterpret_cast<__half2*>(&u));
            acc[v].x += a.x;
            acc[v].y += a.y;
        }
    }

    float inv = 1.0f / (float)max(end - beg, 1);
    uint32_t* o = reinterpret_cast<uint32_t*>(agg) + (size_t)w * rowu + lane * H2;
    #pragma unroll
    for (int v = 0; v < H2; v++) {
        __half2 hv = __floats2half2_rn(acc[v].x * inv, acc[v].y * inv);
        o[v] = *reinterpret_cast<uint32_t*>(&hv);
    }
}

// ---------------- fp16 mma.sync m16n8k16 fused SAGE GEMM (ldmatrix fragments) ----------------
// 256 threads, 2x4 warp grid, 128 x NPAD tile, K'=2K concat, 32-k chunks,
// cp.async double-buffer. Fragments via ldmatrix.m8n8.x4 (conflict-free with
// STRH=40: 8 row addrs cover all 32 banks; 80B stride keeps 16B alignment).
#define STRH 40

template<int NPAD, int OUTH>
__global__ __launch_bounds__(256, 1) void sage_gemm_h(
    const __half* __restrict__ Adst, const __half* __restrict__ Agg,
    const __half* __restrict__ Bt, const float* __restrict__ bias,
    void* __restrict__ outv, int M, int K, int N_out, int relu)
{
    constexpr int NT = NPAD / 32;
    extern __shared__ __half smh[];
    __half* AsBase = smh;                          // [2][128][STRH]
    __half* BsBase = smh + 2 * 128 * STRH;         // [2][NPAD][STRH]

    const uint32_t sb_a = smem_u32(AsBase);
    const uint32_t sb_b = smem_u32(BsBase);
    const int tid = threadIdx.x;
    const int wid = tid >> 5, lane = tid & 31;
    const int wm = wid & 1, wn = wid >> 1;
    const int m0 = blockIdx.x * 128;
    const int K2 = 2 * K;
    const int nc = K2 / 32;

    // ldmatrix per-lane address components
    const int a_row = (lane & 15);                 // row offset within 16
    const int a_col = (lane & 16) ? 8 : 0;         // k offset
    const int b_row = (lane & 7);
    const int b_col = (lane & 8) ? 8 : 0;
    const int b_tile = (lane >> 4) & 1;            // which n-tile of the pair

    float acc[4][NT][4];
    #pragma unroll
    for (int m = 0; m < 4; m++)
        #pragma unroll
        for (int n = 0; n < NT; n++)
            #pragma unroll
            for (int j = 0; j < 4; j++) acc[m][n][j] = 0.f;

    auto issue = [&](int ic) {
        const int buf = ic & 1;
        const int kb_b = ic * 32;
        int kb = kb_b;
        const __half* __restrict__ Ap = Adst;
        if (kb >= K) { Ap = Agg; kb -= K; }
        #pragma unroll
        for (int t = 0; t < 2; t++) {
            int idx = tid + t * 256;
            int r = idx >> 2, q = idx & 3;
            int gr = m0 + r;
            int grc = gr < M ? gr : (M - 1);
            const __half* src = Ap + (size_t)grc * K + kb + q * 8;
            uint32_t dst = sb_a + (uint32_t)((buf * 128 + r) * STRH + q * 8) * 2u;
            cp16(dst, src, gr < M ? 16 : 0);
        }
        #pragma unroll
        for (int t = 0; t < NPAD / 64; t++) {
            int idx = tid + t * 256;
            int n = idx >> 2, q = idx & 3;
            const __half* src = Bt + (size_t)n * K2 + kb_b + q * 8;
            uint32_t dst = sb_b + (uint32_t)((buf * NPAD + n) * STRH + q * 8) * 2u;
            cp16(dst, src, 16);
        }
        asm volatile("cp.async.commit_group;" ::: "memory");
    };

    issue(0);
    for (int ic = 0; ic < nc; ic++) {
        if (ic + 1 < nc) {
            issue(ic + 1);
            asm volatile("cp.async.wait_group 1;" ::: "memory");
        } else {
            asm volatile("cp.async.wait_group 0;" ::: "memory");
        }
        __syncthreads();

        const uint32_t sbA = sb_a + (uint32_t)((ic & 1) * 128 * STRH) * 2u;
        const uint32_t sbB = sb_b + (uint32_t)((ic & 1) * NPAD * STRH) * 2u;

        #pragma unroll
        for (int s = 0; s < 2; s++) {              // two k16 steps per 32-k chunk
            const int cs = s * 16;
            uint32_t af[4][4];
            #pragma unroll
            for (int m = 0; m < 4; m++) {
                int r = wm * 64 + m * 16 + a_row;
                uint32_t addr = sbA + (uint32_t)(r * STRH + cs + a_col) * 2u;
                LDSM_X4(af[m][0], af[m][1], af[m][2], af[m][3], addr);
            }
            uint32_t bf[NT][2];
            #pragma unroll
            for (int p = 0; p < NT / 2; p++) {
                int nn = wn * (NPAD / 4) + (2 * p + b_tile) * 8 + b_row;
                uint32_t addr = sbB + (uint32_t)(nn * STRH + cs + b_col) * 2u;
                LDSM_X4(bf[2 * p][0], bf[2 * p][1], bf[2 * p + 1][0], bf[2 * p + 1][1], addr);
            }
            #pragma unroll
            for (int m = 0; m < 4; m++)
                #pragma unroll
                for (int n = 0; n < NT; n++)
                    mma_f16(acc[m][n], af[m], bf[n]);
        }
        __syncthreads();
    }

    // epilogue: bias + optional relu; fp16 (half2) or fp32 scalar output
    const int g = lane >> 2, tg = lane & 3;
    #pragma unroll
    for (int m = 0; m < 4; m++) {
        const int r0 = m0 + wm * 64 + m * 16 + g;
        #pragma unroll
        for (int n = 0; n < NT; n++) {
            const int c0 = wn * (NPAD / 4) + n * 8 + tg * 2;
            #pragma unroll
            for (int i = 0; i < 2; i++) {
                const int r = r0 + i * 8;
                if (r >= M) continue;
                float v0 = acc[m][n][i * 2 + 0] + bias[c0 < N_out ? c0 : 0];
                float v1 = acc[m][n][i * 2 + 1] + bias[(c0 + 1) < N_out ? (c0 + 1) : 0];
                if (relu) { v0 = fmaxf(v0, 0.f); v1 = fmaxf(v1, 0.f); }
                if (OUTH) {
                    __half2 hv = __floats2half2_rn(v0, v1);
                    *reinterpret_cast<__half2*>(
                        (__half*)outv + (size_t)r * N_out + c0) = hv;
                } else {
                    float* outp = (float*)outv;
                    if (c0 < N_out)     outp[(size_t)r * N_out + c0] = v0;
                    if (c0 + 1 < N_out) outp[(size_t)r * N_out + c0 + 1] = v1;
                }
            }
        }
    }
}

#define SMEMH256 ((2 * 128 * STRH + 2 * 256 * STRH) * 2)   // 61440 B
#define SMEMH64  ((2 * 128 * STRH + 2 * 64 * STRH) * 2)    // 30720 B

// ---------------- host orchestration ----------------
extern "C" void kernel_launch(void* const* d_in, const int* in_sizes, int n_in,
                              void* d_out, int out_size) {
    const float* x    = (const float*)d_in[0];
    const int*   src0 = (const int*)  d_in[1];
    const int*   dst0 = (const int*)  d_in[2];
    const int*   src1 = (const int*)  d_in[3];
    const int*   dst1 = (const int*)  d_in[4];
    const int*   src2 = (const int*)  d_in[5];
    const int*   dst2 = (const int*)  d_in[6];
    const float* Ws0  = (const float*)d_in[7];
    const float* Wn0  = (const float*)d_in[8];
    const float* b0   = (const float*)d_in[9];
    const float* Ws1  = (const float*)d_in[10];
    const float* Wn1  = (const float*)d_in[11];
    const float* b1   = (const float*)d_in[12];
    const float* Ws2  = (const float*)d_in[13];
    const float* Wn2  = (const float*)d_in[14];
    const float* b2   = (const float*)d_in[15];
    float* out = (float*)d_out;

    __half *xh, *agg0h, *h1h, *agg1h, *h2h, *agg2h, *bt0h, *bt1h, *bt2h;
    int *rp0, *rp1, *rp2, *ei0, *ei1, *ei2;
    cudaGetSymbolAddress((void**)&xh,    g_xh);
    cudaGetSymbolAddress((void**)&agg0h, g_agg0h);
    cudaGetSymbolAddress((void**)&h1h,   g_h1h);
    cudaGetSymbolAddress((void**)&agg1h, g_agg1h);
    cudaGetSymbolAddress((void**)&h2h,   g_h2h);
    cudaGetSymbolAddress((void**)&agg2h, g_agg2h);
    cudaGetSymbolAddress((void**)&rp0, g_rp0);
    cudaGetSymbolAddress((void**)&rp1, g_rp1);
    cudaGetSymbolAddress((void**)&rp2, g_rp2);
    cudaGetSymbolAddress((void**)&ei0, g_eidx0);
    cudaGetSymbolAddress((void**)&ei1, g_eidx1);
    cudaGetSymbolAddress((void**)&ei2, g_eidx2);
    cudaGetSymbolAddress((void**)&bt0h, g_Bt0h);
    cudaGetSymbolAddress((void**)&bt1h, g_Bt1h);
    cudaGetSymbolAddress((void**)&bt2h, g_Bt2h);

    cudaFuncSetAttribute(sage_gemm_h<256, 1>,
                         cudaFuncAttributeMaxDynamicSharedMemorySize, SMEMH256);
    cudaFuncSetAttribute(sage_gemm_h<64, 0>,
                         cudaFuncAttributeMaxDynamicSharedMemorySize, SMEMH64);

    const int TB = 256;
    const int BT_TOT = 65536 + 131072 + 32768;
    const long long XN4 = (long long)300000 * D_IN / 4;

    // ---- batched Bt(fp16) build + cnt zero ----
    build_bt_zero_kernel<<<(BT_TOT + TB - 1) / TB, TB>>>(Ws0, Wn0, Ws1, Wn1, Ws2, Wn2);

    // ---- x -> fp16 ----
    {
        long long g = (XN4 + TB - 1) / TB;
        if (g > 118784) g = 118784;
        cvt_x_kernel<<<(int)g, TB>>>((const float4*)x, (uint2*)xh, XN4);
    }

    // ---- batched CSR build ----
    hist_all_kernel<<<(ETOT + TB - 1) / TB, TB>>>(dst0, dst1, dst2);
    scan1_all_kernel<<<NBT, TB>>>();
    scan23_all_kernel<<<NBT, TB>>>();
    fillidx_all_kernel<<<(ETOT + TB - 1) / TB, TB>>>(src0, dst0, src1, dst1, src2, dst2);

    // ---- layer 0: x_h[300000,128] -> h1_h[100000,256], relu ----
    gather_h_kernel<2><<<(NDST0 * 32 + TB - 1) / TB, TB>>>(
        xh, rp0, ei0, agg0h, NDST0);
    sage_gemm_h<256, 1><<<(NDST0 + 127) / 128, 256, SMEMH256>>>(
        xh, agg0h, bt0h, b0, h1h, NDST0, D_IN, 256, 1);

    // ---- layer 1: h1_h -> h2_h[20000,256], relu ----
    gather_h_kernel<4><<<(NDST1 * 32 + TB - 1) / TB, TB>>>(
        h1h, rp1, ei1, agg1h, NDST1);
    sage_gemm_h<256, 1><<<(NDST1 + 127) / 128, 256, SMEMH256>>>(
        h1h, agg1h, bt1h, b1, h2h, NDST1, D_H, 256, 1);

    // ---- layer 2: h2_h -> out[4096,47] fp32, no relu ----
    gather_h_kernel<4><<<(NDST2 * 32 + TB - 1) / TB, TB>>>(
        h2h, rp2, ei2, agg2h, NDST2);
    sage_gemm_h<64, 0><<<(NDST2 + 127) / 128, 256, SMEMH64>>>(
        h2h, agg2h, bt2h, b2, out, NDST2, D_H, 47, 0);
}